// round 13
// baseline (speedup 1.0000x reference)
#include <cuda_runtime.h>
#include <cstdint>

// Binarization (braq high_order_residual, order=2), shape (11008, 4096).
// Inputs: x (float32), mask (int32 0/1). Output float32.
//
// One CTA per row. 512 threads x 8 elems/thread = 4096. Register-resident
// single pass: each global byte touched exactly once (streaming .cs hints).
// 3 block reductions, each with ONE barrier (distinct smem buffers -> no WAR).
//   A: cnt, sum1                         -> mean1
//   B: sum|c1|, sum sign(c1)             -> scale1; mean2 folded algebraically
//   C: sum|c2|                           -> scale2
//   out = m * (b1 + b2)

#define IC       4096
#define THREADS  512
#define F4       2          // float4 chunks per thread (8 elements)
#define NWARP    (THREADS / 32)

__device__ __forceinline__ float sgnf(float c) {
    return (c > 0.f) ? 1.f : ((c < 0.f) ? -1.f : 0.f);   // jnp.sign: sign(0)=0
}

__global__ void __launch_bounds__(THREADS, 2)
binarization_kernel(const float* __restrict__ x,
                    const int* __restrict__ mask,
                    float* __restrict__ out)
{
    const size_t row = blockIdx.x;
    const float4* __restrict__ x4 = reinterpret_cast<const float4*>(x  + row * IC);
    const int4*   __restrict__ m4 = reinterpret_cast<const int4*>(mask + row * IC);
    float4*       __restrict__ o4 = reinterpret_cast<float4*>(out      + row * IC);

    const int tid  = threadIdx.x;
    const int lane = tid & 31;
    const int wid  = tid >> 5;

    // ---- load: front-batched 128-bit streaming LDGs (MLP=4) ----
    float v[8];           // masked x (0 outside mask)
    unsigned mb = 0u;     // 8-bit mask word
    #pragma unroll
    for (int j = 0; j < F4; j++) {
        float4 xv = __ldcs(&x4[tid + THREADS * j]);
        int4   mv = __ldcs(&m4[tid + THREADS * j]);
        const int b = j * 4;
        v[b + 0] = mv.x ? xv.x : 0.f;  mb |= (mv.x ? 1u : 0u) << (b + 0);
        v[b + 1] = mv.y ? xv.y : 0.f;  mb |= (mv.y ? 1u : 0u) << (b + 1);
        v[b + 2] = mv.z ? xv.z : 0.f;  mb |= (mv.z ? 1u : 0u) << (b + 2);
        v[b + 3] = mv.w ? xv.w : 0.f;  mb |= (mv.w ? 1u : 0u) << (b + 3);
    }

    // Distinct buffers per reduction stage -> no WAR hazard -> 1 barrier each.
    __shared__ float sA0[NWARP], sA1[NWARP];
    __shared__ float sB0[NWARP], sB1[NWARP];
    __shared__ float sC0[NWARP];

    auto warp_red2 = [&](float& a, float& b) {
        #pragma unroll
        for (int o = 16; o; o >>= 1) {
            a += __shfl_xor_sync(0xffffffffu, a, o);
            b += __shfl_xor_sync(0xffffffffu, b, o);
        }
    };

    // ---- pass A: count + masked sum ----
    float cnt = 0.f, sum1 = 0.f;
    #pragma unroll
    for (int i = 0; i < 8; i++) {
        cnt  += ((mb >> i) & 1u) ? 1.f : 0.f;
        sum1 += v[i];
    }
    warp_red2(cnt, sum1);
    if (lane == 0) { sA0[wid] = cnt; sA1[wid] = sum1; }
    __syncthreads();
    cnt = 0.f; sum1 = 0.f;
    #pragma unroll
    for (int w = 0; w < NWARP; w++) { cnt += sA0[w]; sum1 += sA1[w]; }

    const bool  has   = cnt > 0.f;
    const float inv   = 1.f / fmaxf(cnt, 1.f);
    const float mean1 = has ? sum1 * inv : 0.f;

    // ---- pass B: sum|c1|, sum sign(c1) ----
    float sabs1 = 0.f, ssign1 = 0.f;
    #pragma unroll
    for (int i = 0; i < 8; i++) {
        const float mfi = ((mb >> i) & 1u) ? 1.f : 0.f;
        const float c1  = (v[i] - mean1) * mfi;
        sabs1  += fabsf(c1);
        ssign1 += sgnf(c1);
    }
    warp_red2(sabs1, ssign1);
    if (lane == 0) { sB0[wid] = sabs1; sB1[wid] = ssign1; }
    __syncthreads();
    sabs1 = 0.f; ssign1 = 0.f;
    #pragma unroll
    for (int w = 0; w < NWARP; w++) { sabs1 += sB0[w]; ssign1 += sB1[w]; }

    const float scale1 = has ? sabs1 * inv : 0.f;
    // mean of r2=(x-b1)*m, with sum(b1 over mask) = scale1*ssign1 + mean1*cnt
    const float mean2  = has ? (sum1 - scale1 * ssign1 - mean1 * cnt) * inv : 0.f;

    // ---- pass C: sum|c2| ----
    float sabs2 = 0.f;
    #pragma unroll
    for (int i = 0; i < 8; i++) {
        const float mfi = ((mb >> i) & 1u) ? 1.f : 0.f;
        const float c1  = (v[i] - mean1) * mfi;
        const float b1  = sgnf(c1) * scale1 + mean1;
        const float r2  = (v[i] - b1) * mfi;
        const float c2  = (r2 - mean2) * mfi;
        sabs2 += fabsf(c2);
    }
    #pragma unroll
    for (int o = 16; o; o >>= 1) sabs2 += __shfl_xor_sync(0xffffffffu, sabs2, o);
    if (lane == 0) sC0[wid] = sabs2;
    __syncthreads();
    sabs2 = 0.f;
    #pragma unroll
    for (int w = 0; w < NWARP; w++) sabs2 += sC0[w];

    const float scale2 = has ? sabs2 * inv : 0.f;

    // ---- final: compute + 128-bit streaming stores ----
    #pragma unroll
    for (int j = 0; j < F4; j++) {
        float4 ov;
        float* po = &ov.x;
        #pragma unroll
        for (int k = 0; k < 4; k++) {
            const int   i   = j * 4 + k;
            const float mfi = ((mb >> i) & 1u) ? 1.f : 0.f;
            const float c1  = (v[i] - mean1) * mfi;
            const float b1  = sgnf(c1) * scale1 + mean1;
            const float r2  = (v[i] - b1) * mfi;
            const float c2  = (r2 - mean2) * mfi;
            const float b2  = sgnf(c2) * scale2 + mean2;
            po[k] = mfi * (b1 + b2);
        }
        __stcs(&o4[tid + THREADS * j], ov);
    }
}

extern "C" void kernel_launch(void* const* d_in, const int* in_sizes, int n_in,
                              void* d_out, int out_size)
{
    const float* x    = (const float*)d_in[0];
    const int*   mask = (const int*)d_in[1];
    float*       out  = (float*)d_out;

    const int rows = in_sizes[0] / IC;   // 11008
    binarization_kernel<<<rows, THREADS>>>(x, mask, out);
}

// round 16
// speedup vs baseline: 1.0624x; 1.0624x over previous
#include <cuda_runtime.h>
#include <cstdint>

// Binarization (braq high_order_residual, order=2), shape (11008, 4096).
// Inputs: x (float32), mask (int32 0/1). Output float32.
//
// One CTA per row. 256 threads x 16 elems/thread = 4096 (R10 shape — proven
// fastest; wider CTAs regress via O(threads*NWARP) broadcast-sum cost).
// Register-resident single pass: each global byte touched exactly once
// (streaming .cs hints). 3 block reductions, ONE barrier each (distinct smem
// buffers -> no WAR hazard).
//   A: cnt (popc), sum1                  -> mean1
//   B: sum|c1|, sum sign(c1)             -> scale1; mean2 folded algebraically
//   C: sum|c2|                           -> scale2
//   out = m * (b1 + b2)
// sign() handling: exact sign(0)=0 (sgnf) wherever it reaches a reduction or
// the output (ssign1, b2). b1 uses copysignf (sign(0)->+1): safe because b1
// only feeds r2=(v-b1)*mfi which is masked, and in-mask c1==0 has measure 0.

#define IC       4096
#define THREADS  256
#define F4       4          // float4 chunks per thread (16 elements)
#define NWARP    (THREADS / 32)

__device__ __forceinline__ float sgnf(float c) {
    return (c > 0.f) ? 1.f : ((c < 0.f) ? -1.f : 0.f);   // jnp.sign: sign(0)=0
}

__global__ void __launch_bounds__(THREADS, 1)
binarization_kernel(const float* __restrict__ x,
                    const int* __restrict__ mask,
                    float* __restrict__ out)
{
    const size_t row = blockIdx.x;
    const float4* __restrict__ x4 = reinterpret_cast<const float4*>(x  + row * IC);
    const int4*   __restrict__ m4 = reinterpret_cast<const int4*>(mask + row * IC);
    float4*       __restrict__ o4 = reinterpret_cast<float4*>(out      + row * IC);

    const int tid  = threadIdx.x;
    const int lane = tid & 31;
    const int wid  = tid >> 5;

    // ---- load: front-batched 128-bit streaming LDGs (MLP=8) ----
    float v[16];          // masked x (0 outside mask)
    unsigned mb = 0u;     // 16-bit mask word
    #pragma unroll
    for (int j = 0; j < F4; j++) {
        float4 xv = __ldcs(&x4[tid + THREADS * j]);
        int4   mv = __ldcs(&m4[tid + THREADS * j]);
        const int b = j * 4;
        v[b + 0] = mv.x ? xv.x : 0.f;  mb |= (mv.x ? 1u : 0u) << (b + 0);
        v[b + 1] = mv.y ? xv.y : 0.f;  mb |= (mv.y ? 1u : 0u) << (b + 1);
        v[b + 2] = mv.z ? xv.z : 0.f;  mb |= (mv.z ? 1u : 0u) << (b + 2);
        v[b + 3] = mv.w ? xv.w : 0.f;  mb |= (mv.w ? 1u : 0u) << (b + 3);
    }

    // Distinct buffers per reduction stage -> 1 barrier each.
    __shared__ float sA0[NWARP], sA1[NWARP];
    __shared__ float sB0[NWARP], sB1[NWARP];
    __shared__ float sC0[NWARP];

    auto warp_red2 = [&](float& a, float& b) {
        #pragma unroll
        for (int o = 16; o; o >>= 1) {
            a += __shfl_xor_sync(0xffffffffu, a, o);
            b += __shfl_xor_sync(0xffffffffu, b, o);
        }
    };

    // ---- pass A: count (popc) + masked sum ----
    float cnt  = (float)__popc(mb);
    float sum1 = 0.f;
    #pragma unroll
    for (int i = 0; i < 16; i++) sum1 += v[i];
    warp_red2(cnt, sum1);
    if (lane == 0) { sA0[wid] = cnt; sA1[wid] = sum1; }
    __syncthreads();
    cnt = 0.f; sum1 = 0.f;
    #pragma unroll
    for (int w = 0; w < NWARP; w++) { cnt += sA0[w]; sum1 += sA1[w]; }

    const bool  has   = cnt > 0.f;
    const float inv   = 1.f / fmaxf(cnt, 1.f);
    const float mean1 = has ? sum1 * inv : 0.f;

    // ---- pass B: sum|c1|, sum sign(c1) ----
    float sabs1 = 0.f, ssign1 = 0.f;
    #pragma unroll
    for (int i = 0; i < 16; i++) {
        const float mfi = ((mb >> i) & 1u) ? 1.f : 0.f;
        const float c1  = (v[i] - mean1) * mfi;
        sabs1  += fabsf(c1);
        ssign1 += sgnf(c1);          // exact sign(0)=0: feeds mean2 fold
    }
    warp_red2(sabs1, ssign1);
    if (lane == 0) { sB0[wid] = sabs1; sB1[wid] = ssign1; }
    __syncthreads();
    sabs1 = 0.f; ssign1 = 0.f;
    #pragma unroll
    for (int w = 0; w < NWARP; w++) { sabs1 += sB0[w]; ssign1 += sB1[w]; }

    const float scale1 = has ? sabs1 * inv : 0.f;
    // mean of r2=(x-b1)*m, with sum(b1 over mask) = scale1*ssign1 + mean1*cnt
    const float mean2  = has ? (sum1 - scale1 * ssign1 - mean1 * cnt) * inv : 0.f;

    // ---- pass C: sum|c2| ----
    float sabs2 = 0.f;
    #pragma unroll
    for (int i = 0; i < 16; i++) {
        const float mfi = ((mb >> i) & 1u) ? 1.f : 0.f;
        const float c1  = (v[i] - mean1) * mfi;
        const float b1  = copysignf(scale1, c1) + mean1;   // mask-safe (see header)
        const float r2  = (v[i] - b1) * mfi;
        const float c2  = (r2 - mean2) * mfi;
        sabs2 += fabsf(c2);
    }
    #pragma unroll
    for (int o = 16; o; o >>= 1) sabs2 += __shfl_xor_sync(0xffffffffu, sabs2, o);
    if (lane == 0) sC0[wid] = sabs2;
    __syncthreads();
    sabs2 = 0.f;
    #pragma unroll
    for (int w = 0; w < NWARP; w++) sabs2 += sC0[w];

    const float scale2 = has ? sabs2 * inv : 0.f;

    // ---- final: compute + 128-bit streaming stores ----
    #pragma unroll
    for (int j = 0; j < F4; j++) {
        float4 ov;
        float* po = &ov.x;
        #pragma unroll
        for (int k = 0; k < 4; k++) {
            const int   i   = j * 4 + k;
            const float mfi = ((mb >> i) & 1u) ? 1.f : 0.f;
            const float c1  = (v[i] - mean1) * mfi;
            const float b1  = copysignf(scale1, c1) + mean1;  // mask-safe
            const float r2  = (v[i] - b1) * mfi;
            const float c2  = (r2 - mean2) * mfi;
            const float b2  = sgnf(c2) * scale2 + mean2;      // exact: reaches output
            po[k] = mfi * (b1 + b2);
        }
        __stcs(&o4[tid + THREADS * j], ov);
    }
}

extern "C" void kernel_launch(void* const* d_in, const int* in_sizes, int n_in,
                              void* d_out, int out_size)
{
    const float* x    = (const float*)d_in[0];
    const int*   mask = (const int*)d_in[1];
    float*       out  = (float*)d_out;

    const int rows = in_sizes[0] / IC;   // 11008
    binarization_kernel<<<rows, THREADS>>>(x, mask, out);
}

// round 17
// speedup vs baseline: 1.3045x; 1.2279x over previous
#include <cuda_runtime.h>
#include <cstdint>

// Binarization (braq high_order_residual, order=2), shape (11008, 4096).
// Inputs: x (float32), mask (int32 0/1). Output float32.
//
// One CTA per row. 256 threads x 16 elems/thread = 4096.
// __launch_bounds__(256, 3) pins ptxas to <=80 regs -> 3 CTAs/SM (R16 showed
// 82 regs silently rounds to 88 -> 2 CTAs/SM -> occupancy cliff -> 106us).
// Register-resident single pass: each global byte touched exactly once
// (streaming .cs hints). 3 block reductions, ONE barrier each (distinct smem
// buffers -> no WAR hazard).
//   A: cnt (popc), sum1                  -> mean1
//   B: sum|c1|, sum sign(c1)             -> scale1; mean2 folded algebraically
//   C: sum|c2|                           -> scale2
//   out = m * (b1 + b2)
// sign() handling: exact sign(0)=0 (sgnf) kept where it feeds the mean2 fold
// (ssign1). b1 and b2 use copysignf (sign(0)->+1): safe because both only
// reach the output through mask-multiplied terms (r2=(v-b1)*mfi and
// po=mfi*(b1+b2)), and in-mask c1==0 / c2==0 have measure zero.
// (Empirically confirmed: R16 rel_err bit-identical to R10's sgnf version.)

#define IC       4096
#define THREADS  256
#define F4       4          // float4 chunks per thread (16 elements)
#define NWARP    (THREADS / 32)

__device__ __forceinline__ float sgnf(float c) {
    return (c > 0.f) ? 1.f : ((c < 0.f) ? -1.f : 0.f);   // jnp.sign: sign(0)=0
}

__global__ void __launch_bounds__(THREADS, 3)
binarization_kernel(const float* __restrict__ x,
                    const int* __restrict__ mask,
                    float* __restrict__ out)
{
    const size_t row = blockIdx.x;
    const float4* __restrict__ x4 = reinterpret_cast<const float4*>(x  + row * IC);
    const int4*   __restrict__ m4 = reinterpret_cast<const int4*>(mask + row * IC);
    float4*       __restrict__ o4 = reinterpret_cast<float4*>(out      + row * IC);

    const int tid  = threadIdx.x;
    const int lane = tid & 31;
    const int wid  = tid >> 5;

    // ---- load: front-batched 128-bit streaming LDGs (MLP=8) ----
    float v[16];          // masked x (0 outside mask)
    unsigned mb = 0u;     // 16-bit mask word
    #pragma unroll
    for (int j = 0; j < F4; j++) {
        float4 xv = __ldcs(&x4[tid + THREADS * j]);
        int4   mv = __ldcs(&m4[tid + THREADS * j]);
        const int b = j * 4;
        v[b + 0] = mv.x ? xv.x : 0.f;  mb |= (mv.x ? 1u : 0u) << (b + 0);
        v[b + 1] = mv.y ? xv.y : 0.f;  mb |= (mv.y ? 1u : 0u) << (b + 1);
        v[b + 2] = mv.z ? xv.z : 0.f;  mb |= (mv.z ? 1u : 0u) << (b + 2);
        v[b + 3] = mv.w ? xv.w : 0.f;  mb |= (mv.w ? 1u : 0u) << (b + 3);
    }

    // Distinct buffers per reduction stage -> 1 barrier each.
    __shared__ float sA0[NWARP], sA1[NWARP];
    __shared__ float sB0[NWARP], sB1[NWARP];
    __shared__ float sC0[NWARP];

    auto warp_red2 = [&](float& a, float& b) {
        #pragma unroll
        for (int o = 16; o; o >>= 1) {
            a += __shfl_xor_sync(0xffffffffu, a, o);
            b += __shfl_xor_sync(0xffffffffu, b, o);
        }
    };

    // ---- pass A: count (popc) + masked sum ----
    float cnt  = (float)__popc(mb);
    float sum1 = 0.f;
    #pragma unroll
    for (int i = 0; i < 16; i++) sum1 += v[i];
    warp_red2(cnt, sum1);
    if (lane == 0) { sA0[wid] = cnt; sA1[wid] = sum1; }
    __syncthreads();
    cnt = 0.f; sum1 = 0.f;
    #pragma unroll
    for (int w = 0; w < NWARP; w++) { cnt += sA0[w]; sum1 += sA1[w]; }

    const bool  has   = cnt > 0.f;
    const float inv   = 1.f / fmaxf(cnt, 1.f);
    const float mean1 = has ? sum1 * inv : 0.f;

    // ---- pass B: sum|c1|, sum sign(c1) ----
    float sabs1 = 0.f, ssign1 = 0.f;
    #pragma unroll
    for (int i = 0; i < 16; i++) {
        const float mfi = ((mb >> i) & 1u) ? 1.f : 0.f;
        const float c1  = (v[i] - mean1) * mfi;
        sabs1  += fabsf(c1);
        ssign1 += sgnf(c1);          // exact sign(0)=0: feeds mean2 fold
    }
    warp_red2(sabs1, ssign1);
    if (lane == 0) { sB0[wid] = sabs1; sB1[wid] = ssign1; }
    __syncthreads();
    sabs1 = 0.f; ssign1 = 0.f;
    #pragma unroll
    for (int w = 0; w < NWARP; w++) { sabs1 += sB0[w]; ssign1 += sB1[w]; }

    const float scale1 = has ? sabs1 * inv : 0.f;
    // mean of r2=(x-b1)*m, with sum(b1 over mask) = scale1*ssign1 + mean1*cnt
    const float mean2  = has ? (sum1 - scale1 * ssign1 - mean1 * cnt) * inv : 0.f;

    // ---- pass C: sum|c2| ----
    float sabs2 = 0.f;
    #pragma unroll
    for (int i = 0; i < 16; i++) {
        const float mfi = ((mb >> i) & 1u) ? 1.f : 0.f;
        const float c1  = (v[i] - mean1) * mfi;
        const float b1  = copysignf(scale1, c1) + mean1;   // mask-safe (see header)
        const float r2  = (v[i] - b1) * mfi;
        const float c2  = (r2 - mean2) * mfi;
        sabs2 += fabsf(c2);
    }
    #pragma unroll
    for (int o = 16; o; o >>= 1) sabs2 += __shfl_xor_sync(0xffffffffu, sabs2, o);
    if (lane == 0) sC0[wid] = sabs2;
    __syncthreads();
    sabs2 = 0.f;
    #pragma unroll
    for (int w = 0; w < NWARP; w++) sabs2 += sC0[w];

    const float scale2 = has ? sabs2 * inv : 0.f;

    // ---- final: compute + 128-bit streaming stores ----
    #pragma unroll
    for (int j = 0; j < F4; j++) {
        float4 ov;
        float* po = &ov.x;
        #pragma unroll
        for (int k = 0; k < 4; k++) {
            const int   i   = j * 4 + k;
            const float mfi = ((mb >> i) & 1u) ? 1.f : 0.f;
            const float c1  = (v[i] - mean1) * mfi;
            const float b1  = copysignf(scale1, c1) + mean1;  // mask-safe
            const float r2  = (v[i] - b1) * mfi;
            const float c2  = (r2 - mean2) * mfi;
            const float b2  = copysignf(scale2, c2) + mean2;  // mask-safe (po=mfi*..)
            po[k] = mfi * (b1 + b2);
        }
        __stcs(&o4[tid + THREADS * j], ov);
    }
}

extern "C" void kernel_launch(void* const* d_in, const int* in_sizes, int n_in,
                              void* d_out, int out_size)
{
    const float* x    = (const float*)d_in[0];
    const int*   mask = (const int*)d_in[1];
    float*       out  = (float*)d_out;

    const int rows = in_sizes[0] / IC;   // 11008
    binarization_kernel<<<rows, THREADS>>>(x, mask, out);
}